// round 1
// baseline (speedup 1.0000x reference)
#include <cuda_runtime.h>

// QuantizedLinear(5 -> 10, bits=2) over 4M tokens, fp32.
//   scale[o] = max(|w[o,:]|) / qmax, qmax = 1 (bits=2), clamped >= 1e-8
//   w_q = clip(rint(w/scale), -2, 1); w_deq = w_q * scale
//   out = x @ w_deq^T + bias
//
// Streaming/bandwidth-bound: stage x and out tiles through shared memory so
// both global load and store phases are fully coalesced float4 accesses.

#define THREADS 256
#define TPB_TOKENS 256            // tokens per block (1 per thread)
#define IN_F 5
#define OUT_F 10

__global__ __launch_bounds__(THREADS)
void qlinear2bit_kernel(const float* __restrict__ x,
                        const float* __restrict__ w,
                        const float* __restrict__ bias,
                        float* __restrict__ out,
                        int n_tokens)
{
    __shared__ float sx[TPB_TOKENS * IN_F];     // 1280 floats
    __shared__ float so[TPB_TOKENS * OUT_F];    // 2560 floats
    __shared__ float sw[OUT_F * IN_F];          // 50 dequantized weights
    __shared__ float sb[OUT_F];

    const int t = threadIdx.x;
    const long long tok0 = (long long)blockIdx.x * TPB_TOKENS;

    // ---- per-block weight dequant (threads 0..9, one output row each) ----
    if (t < OUT_F) {
        float r[IN_F];
        float m = 0.0f;
        #pragma unroll
        for (int c = 0; c < IN_F; c++) {
            r[c] = w[t * IN_F + c];
            m = fmaxf(m, fabsf(r[c]));
        }
        // qmax = 2^(bits-1)-1 = 1  ->  scale = max|w| / 1
        float scale = fmaxf(m, 1e-8f);
        float inv = 1.0f / scale;
        #pragma unroll
        for (int c = 0; c < IN_F; c++) {
            float q = rintf(r[c] * inv);          // round-half-to-even == jnp.round
            q = fminf(fmaxf(q, -2.0f), 1.0f);     // clip to [qmin, qmax]
            sw[t * IN_F + c] = q * scale;
        }
        sb[t] = bias[t];
    }

    // ---- coalesced load of x tile ----
    const long long xbase = tok0 * IN_F;
    const long long xtotal = (long long)n_tokens * IN_F;
    const int nf = (int)((xtotal - xbase < (long long)(TPB_TOKENS * IN_F))
                             ? (xtotal - xbase) : (long long)(TPB_TOKENS * IN_F));
    if (nf == TPB_TOKENS * IN_F) {
        const float4* xg = (const float4*)(x + xbase);   // 5120B-aligned per block
        #pragma unroll
        for (int i = t; i < TPB_TOKENS * IN_F / 4; i += THREADS)
            ((float4*)sx)[i] = xg[i];
    } else {
        for (int i = t; i < nf; i += THREADS)
            sx[i] = x[xbase + i];
    }
    __syncthreads();

    // ---- compute: one token per thread (smem stride-5 reads: conflict-free) ----
    if (tok0 + t < (long long)n_tokens) {
        float xi[IN_F];
        #pragma unroll
        for (int c = 0; c < IN_F; c++) xi[c] = sx[t * IN_F + c];
        #pragma unroll
        for (int o = 0; o < OUT_F; o++) {
            float acc = sb[o];
            #pragma unroll
            for (int c = 0; c < IN_F; c++)
                acc = fmaf(xi[c], sw[o * IN_F + c], acc);
            so[t * OUT_F + o] = acc;
        }
    }
    __syncthreads();

    // ---- coalesced store of out tile ----
    const long long obase = tok0 * OUT_F;
    const long long ototal = (long long)n_tokens * OUT_F;
    const int nof = (int)((ototal - obase < (long long)(TPB_TOKENS * OUT_F))
                              ? (ototal - obase) : (long long)(TPB_TOKENS * OUT_F));
    if (nof == TPB_TOKENS * OUT_F) {
        float4* og = (float4*)(out + obase);             // 10240B-aligned per block
        #pragma unroll
        for (int i = t; i < TPB_TOKENS * OUT_F / 4; i += THREADS)
            og[i] = ((const float4*)so)[i];
    } else {
        for (int i = t; i < nof; i += THREADS)
            out[obase + i] = so[i];
    }
}

extern "C" void kernel_launch(void* const* d_in, const int* in_sizes, int n_in,
                              void* d_out, int out_size)
{
    const float* x    = (const float*)d_in[0];   // [N, 5]
    const float* w    = (const float*)d_in[1];   // [10, 5]
    const float* bias = (const float*)d_in[2];   // [10]
    float* out = (float*)d_out;                  // [N, 10]

    const int n_tokens = in_sizes[0] / IN_F;
    const int grid = (n_tokens + TPB_TOKENS - 1) / TPB_TOKENS;
    qlinear2bit_kernel<<<grid, THREADS>>>(x, w, bias, out, n_tokens);
}